// round 1
// baseline (speedup 1.0000x reference)
#include <cuda_runtime.h>
#include <math.h>

// ---------------- problem constants ----------------
namespace {
constexpr int kB    = 2;
constexpr int kS    = 2048;
constexpr int kR    = kB * kS;     // 4096 tokens
constexpr int kDim  = 1024;
constexpr int kH    = 8;
constexpr int kQC   = 128;
constexpr int kQNope= 96;
constexpr int kQRope= 32;
constexpr int kKVC  = 128;
constexpr int kKRope= 64;
constexpr int kVD   = 256;
constexpr float kEps = 1e-8f;
constexpr float kScale = 0.08838834764831845f;   // 1/sqrt(128)
constexpr float kLogTheta = 9.210340371976184f;  // ln(10000)
}

// ---------------- scratch (static device globals; no allocations allowed) ----
__device__ float g_cq   [kR * kQC];            // 2 MB
__device__ float g_q    [kR * 1024];           // 16 MB  (nope 768 | rope 256, roped in place)
__device__ float g_ckv  [kR * 192];            // 3 MB   (ckv 128 | k_rope 64)
__device__ float g_ckvn [kR * kKVC];           // 2 MB
__device__ float g_krope[kR * kKRope];         // 1 MB
__device__ float g_kvu  [kR * 2560];           // 40 MB  (k_nope 512 | v 2048)
__device__ float g_attn [kR * 2048];           // 32 MB  [b,s,h*256+d]

// ---------------- generic SGEMM: C[M,N] = A[M,K] @ B[K,N] + bias ------------
// 128x128 block tile, BK=8, 8x8 per thread, 256 threads.
// M must be a multiple of 128 and K a multiple of 8 (true for all call sites).
__global__ __launch_bounds__(256) void sgemm_bias_kernel(
    int M, int N, int K,
    const float* __restrict__ A, const float* __restrict__ Bm,
    const float* __restrict__ bias, float* __restrict__ C)
{
    constexpr int BM = 128, BN = 128, BK = 8, TM = 8, TN = 8;
    __shared__ float As[BK][BM];
    __shared__ float Bs[BK][BN];

    const int tid  = threadIdx.x;
    const int tcol = tid & 15;        // 0..15
    const int trow = tid >> 4;        // 0..15
    const int cCol = blockIdx.x;
    const int cRow = blockIdx.y;

    const int aRow = tid >> 1;        // 0..127
    const int aCol = (tid & 1) * 4;   // 0 or 4
    const int bRow = tid >> 5;        // 0..7
    const int bCol = (tid & 31) * 4;  // 0..124

    const float* Ab = A + (size_t)cRow * BM * K;

    float acc[TM][TN];
#pragma unroll
    for (int i = 0; i < TM; i++)
#pragma unroll
        for (int j = 0; j < TN; j++) acc[i][j] = 0.0f;

    for (int k0 = 0; k0 < K; k0 += BK) {
        // stage A (transposed into smem)
        float4 a4 = *(const float4*)(Ab + (size_t)aRow * K + k0 + aCol);
        As[aCol + 0][aRow] = a4.x;
        As[aCol + 1][aRow] = a4.y;
        As[aCol + 2][aRow] = a4.z;
        As[aCol + 3][aRow] = a4.w;
        // stage B
        int gcol = cCol * BN + bCol;
        float4 b4 = make_float4(0.f, 0.f, 0.f, 0.f);
        const float* bp = Bm + (size_t)(k0 + bRow) * N + gcol;
        if (gcol + 3 < N) {
            b4 = *(const float4*)bp;
        } else {
            if (gcol + 0 < N) b4.x = bp[0];
            if (gcol + 1 < N) b4.y = bp[1];
            if (gcol + 2 < N) b4.z = bp[2];
            if (gcol + 3 < N) b4.w = bp[3];
        }
        *(float4*)&Bs[bRow][bCol] = b4;
        __syncthreads();

#pragma unroll
        for (int kk = 0; kk < BK; kk++) {
            float ar[TM], br[TN];
#pragma unroll
            for (int i = 0; i < TM; i++) ar[i] = As[kk][trow * TM + i];
#pragma unroll
            for (int j = 0; j < TN; j++) br[j] = Bs[kk][tcol * TN + j];
#pragma unroll
            for (int i = 0; i < TM; i++)
#pragma unroll
                for (int j = 0; j < TN; j++) acc[i][j] += ar[i] * br[j];
        }
        __syncthreads();
    }

#pragma unroll
    for (int i = 0; i < TM; i++) {
        int row = cRow * BM + trow * TM + i;
#pragma unroll
        for (int j = 0; j < TN; j++) {
            int col = cCol * BN + tcol * TN + j;
            if (col < N) C[(size_t)row * N + col] = acc[i][j] + bias[col];
        }
    }
}

// ---------------- RMSNorm in place, width 128, one block per row ------------
__global__ void rmsnorm_inplace_kernel(float* __restrict__ x,
                                       const float* __restrict__ w)
{
    const int row = blockIdx.x;
    const int tid = threadIdx.x;  // 128
    float v = x[(size_t)row * 128 + tid];
    float ss = v * v;
#pragma unroll
    for (int o = 16; o > 0; o >>= 1) ss += __shfl_xor_sync(0xffffffffu, ss, o);
    __shared__ float red[4];
    if ((tid & 31) == 0) red[tid >> 5] = ss;
    __syncthreads();
    float sum = red[0] + red[1] + red[2] + red[3];
    float inv = rsqrtf(sum * (1.0f / 128.0f) + kEps);
    x[(size_t)row * 128 + tid] = w[tid] * v * inv;
}

// ---------------- RoPE on q (in place), head_dim=32, 8 heads ----------------
__global__ void rope_q_kernel(float* __restrict__ q, const int* __restrict__ pos_ids)
{
    const int row = blockIdx.x;
    const int tid = threadIdx.x;  // 128 = 8 heads * 16 pairs
    const int h = tid >> 4, i = tid & 15;
    float pos = (float)pos_ids[row];
    float inv = expf(-((float)(2 * i) / 32.0f) * kLogTheta);
    float sv, cv;
    sincosf(pos * inv, &sv, &cv);
    float* base = q + (size_t)row * 1024 + 768 + h * 32;
    float xe = base[2 * i], xo = base[2 * i + 1];
    base[2 * i]     = xe * cv - xo * sv;
    base[2 * i + 1] = xe * sv + xo * cv;
}

// --------- ckv post: rmsnorm(ckv[0:128]) -> ckvn ; rope(ckv[128:192]) -------
__global__ void ckv_post_kernel(const float* __restrict__ ckv,
                                const float* __restrict__ w,
                                const int* __restrict__ pos_ids,
                                float* __restrict__ ckvn,
                                float* __restrict__ krope)
{
    const int row = blockIdx.x;
    const int tid = threadIdx.x;  // 128
    float v = ckv[(size_t)row * 192 + tid];
    float ss = v * v;
#pragma unroll
    for (int o = 16; o > 0; o >>= 1) ss += __shfl_xor_sync(0xffffffffu, ss, o);
    __shared__ float red[4];
    if ((tid & 31) == 0) red[tid >> 5] = ss;
    __syncthreads();
    float sum = red[0] + red[1] + red[2] + red[3];
    float inv = rsqrtf(sum * (1.0f / 128.0f) + kEps);
    ckvn[(size_t)row * 128 + tid] = w[tid] * v * inv;

    if (tid < 32) {
        const int i = tid;
        float pos = (float)pos_ids[row];
        float invf = expf(-((float)(2 * i) / 64.0f) * kLogTheta);
        float sv, cv;
        sincosf(pos * invf, &sv, &cv);
        const float* rb = ckv + (size_t)row * 192 + 128;
        float xe = rb[2 * i], xo = rb[2 * i + 1];
        krope[(size_t)row * 64 + 2 * i]     = xe * cv - xo * sv;
        krope[(size_t)row * 64 + 2 * i + 1] = xe * sv + xo * cv;
    }
}

// ---------------- flash attention, fp32 -------------------------------------
// Grid: (S/64, H, B). 256 threads. Thread (r=tid/4, g=tid&3) owns score cols
// g*8..g*8+7 and output cols g*64..g*64+63 of query row r.
constexpr int kQLD = 132, kKLD = 132, kVLD = 260;  // padded strides (floats)
constexpr int kAttnSmemBytes = (64 * kQLD + 32 * kKLD + 32 * kVLD) * 4;  // 83968

__global__ __launch_bounds__(256, 2) void attn_kernel(
    const float* __restrict__ q, const float* __restrict__ kvu,
    const float* __restrict__ krope, float* __restrict__ out)
{
    constexpr int BQ = 64, BKT = 32;
    extern __shared__ float sm[];
    float* Qs = sm;                  // 64 x 132
    float* Ks = Qs + BQ * kQLD;      // 32 x 132
    float* Vs = Ks + BKT * kKLD;     // 32 x 260

    const int qt = blockIdx.x, h = blockIdx.y, b = blockIdx.z;
    const int tid = threadIdx.x;
    const int r = tid >> 2, g = tid & 3;
    const int q0 = qt * BQ;
    const size_t rowbase = (size_t)b * kS;

    // stage Q tile (nope | roped rope, per head)
    for (int idx = tid; idx < BQ * 128; idx += 256) {
        int rr = idx >> 7, d = idx & 127;
        size_t grow = (rowbase + q0 + rr) * 1024;
        float v = (d < 96) ? q[grow + h * 96 + d]
                           : q[grow + 768 + h * 32 + (d - 96)];
        Qs[rr * kQLD + d] = v;
    }

    float m = -INFINITY, l = 0.0f;
    float acc[64];
#pragma unroll
    for (int c = 0; c < 64; c++) acc[c] = 0.0f;

    for (int kt = 0; kt < kS / BKT; kt++) {
        __syncthreads();
        const int k0 = kt * BKT;
        for (int idx = tid; idx < BKT * 128; idx += 256) {
            int j = idx >> 7, d = idx & 127;
            size_t grow = rowbase + k0 + j;
            float v = (d < 64) ? kvu[grow * 2560 + h * 64 + d]
                               : krope[grow * 64 + (d - 64)];
            Ks[j * kKLD + d] = v;
        }
        for (int idx = tid; idx < BKT * 256; idx += 256) {
            int j = idx >> 8, c = idx & 255;
            size_t grow = rowbase + k0 + j;
            Vs[j * kVLD + c] = kvu[grow * 2560 + 512 + h * 256 + c];
        }
        __syncthreads();

        // scores for 8 key columns
        float s8[8];
#pragma unroll
        for (int jj = 0; jj < 8; jj++) s8[jj] = 0.0f;
        const float* qrow = Qs + r * kQLD;
#pragma unroll 8
        for (int d4 = 0; d4 < 32; d4++) {
            float4 qv = *(const float4*)(qrow + d4 * 4);
#pragma unroll
            for (int jj = 0; jj < 8; jj++) {
                float4 kv4 = *(const float4*)(Ks + (g * 8 + jj) * kKLD + d4 * 4);
                s8[jj] += qv.x * kv4.x + qv.y * kv4.y + qv.z * kv4.z + qv.w * kv4.w;
            }
        }
        float tm = -INFINITY;
#pragma unroll
        for (int jj = 0; jj < 8; jj++) {
            s8[jj] *= kScale;
            tm = fmaxf(tm, s8[jj]);
        }
        tm = fmaxf(tm, __shfl_xor_sync(0xffffffffu, tm, 1));
        tm = fmaxf(tm, __shfl_xor_sync(0xffffffffu, tm, 2));
        const float mnew = fmaxf(m, tm);
        const float corr = __expf(m - mnew);
        float p[8], ps = 0.0f;
#pragma unroll
        for (int jj = 0; jj < 8; jj++) {
            p[jj] = __expf(s8[jj] - mnew);
            ps += p[jj];
        }
        ps += __shfl_xor_sync(0xffffffffu, ps, 1);
        ps += __shfl_xor_sync(0xffffffffu, ps, 2);
        l = l * corr + ps;
        m = mnew;
#pragma unroll
        for (int c = 0; c < 64; c++) acc[c] *= corr;

        // O += P @ V  (P row shared across the 4-thread quad via shfl)
        const int lanebase = (tid & 31) & ~3;
#pragma unroll
        for (int gg = 0; gg < 4; gg++) {
#pragma unroll 2
            for (int jj = 0; jj < 8; jj++) {
                float pj = __shfl_sync(0xffffffffu, p[jj], lanebase + gg, 32);
                const float* vrow = Vs + (gg * 8 + jj) * kVLD + g * 64;
#pragma unroll
                for (int c4 = 0; c4 < 16; c4++) {
                    float4 vv = *(const float4*)(vrow + c4 * 4);
                    acc[c4 * 4 + 0] += pj * vv.x;
                    acc[c4 * 4 + 1] += pj * vv.y;
                    acc[c4 * 4 + 2] += pj * vv.z;
                    acc[c4 * 4 + 3] += pj * vv.w;
                }
            }
        }
    }

    const float invl = 1.0f / l;
    float* orow = out + (rowbase + q0 + r) * 2048 + h * 256 + g * 64;
#pragma unroll
    for (int c4 = 0; c4 < 16; c4++) {
        float4 o;
        o.x = acc[c4 * 4 + 0] * invl;
        o.y = acc[c4 * 4 + 1] * invl;
        o.z = acc[c4 * 4 + 2] * invl;
        o.w = acc[c4 * 4 + 3] * invl;
        *(float4*)(orow + c4 * 4) = o;
    }
}

// ---------------- launch -----------------------------------------------------
extern "C" void kernel_launch(void* const* d_in, const int* in_sizes, int n_in,
                              void* d_out, int out_size)
{
    const float* x         = (const float*)d_in[0];
    const int*   pos       = (const int*)  d_in[1];
    const float* w_dq_w    = (const float*)d_in[2];
    const float* w_dq_b    = (const float*)d_in[3];
    const float* q_norm_w  = (const float*)d_in[4];
    const float* w_uq_w    = (const float*)d_in[5];
    const float* w_uq_b    = (const float*)d_in[6];
    const float* w_dkv_w   = (const float*)d_in[7];
    const float* w_dkv_b   = (const float*)d_in[8];
    const float* kv_norm_w = (const float*)d_in[9];
    const float* w_ukuv_w  = (const float*)d_in[10];
    const float* w_ukuv_b  = (const float*)d_in[11];
    const float* w_o_w     = (const float*)d_in[12];
    const float* w_o_b     = (const float*)d_in[13];
    float* out = (float*)d_out;

    float *cq, *qb, *ckv, *ckvn, *krope, *kvu, *attn;
    cudaGetSymbolAddress((void**)&cq,    g_cq);
    cudaGetSymbolAddress((void**)&qb,    g_q);
    cudaGetSymbolAddress((void**)&ckv,   g_ckv);
    cudaGetSymbolAddress((void**)&ckvn,  g_ckvn);
    cudaGetSymbolAddress((void**)&krope, g_krope);
    cudaGetSymbolAddress((void**)&kvu,   g_kvu);
    cudaGetSymbolAddress((void**)&attn,  g_attn);

    // Q path
    sgemm_bias_kernel<<<dim3(1, kR / 128), 256>>>(kR, 128, 1024, x, w_dq_w, w_dq_b, cq);
    rmsnorm_inplace_kernel<<<kR, 128>>>(cq, q_norm_w);
    sgemm_bias_kernel<<<dim3(8, kR / 128), 256>>>(kR, 1024, 128, cq, w_uq_w, w_uq_b, qb);
    rope_q_kernel<<<kR, 128>>>(qb, pos);

    // KV path
    sgemm_bias_kernel<<<dim3(2, kR / 128), 256>>>(kR, 192, 1024, x, w_dkv_w, w_dkv_b, ckv);
    ckv_post_kernel<<<kR, 128>>>(ckv, kv_norm_w, pos, ckvn, krope);
    sgemm_bias_kernel<<<dim3(20, kR / 128), 256>>>(kR, 2560, 128, ckvn, w_ukuv_w, w_ukuv_b, kvu);

    // Attention
    cudaFuncSetAttribute(attn_kernel, cudaFuncAttributeMaxDynamicSharedMemorySize,
                         kAttnSmemBytes);
    attn_kernel<<<dim3(kS / 64, kH, kB), 256, kAttnSmemBytes>>>(qb, kvu, krope, attn);

    // Output projection
    sgemm_bias_kernel<<<dim3(8, kR / 128), 256>>>(kR, 1024, 2048, attn, w_o_w, w_o_b, out);
}

// round 2
// speedup vs baseline: 11.2826x; 11.2826x over previous
#include <cuda_runtime.h>
#include <math.h>
#include <stdint.h>

// ---------------- problem constants ----------------
namespace {
constexpr int kS = 2048;
constexpr int kR = 4096;               // 2 * 2048 tokens
constexpr float kEps = 1e-8f;
constexpr float kScale = 0.08838834764831845f;   // 1/sqrt(128)
constexpr float kLogTheta = 9.210340371976184f;  // ln(10000)
}

// ---------------- scratch ----------------
__device__ float g_cq   [kR * 128];
__device__ float g_q    [kR * 1024];   // nope 768 | rope 256 (roped in place)
__device__ float g_ckv  [kR * 192];
__device__ float g_ckvn [kR * 128];
__device__ float g_krope[kR * 64];
__device__ float g_kvu  [kR * 2560];   // k_nope 512 | v 2048
__device__ float g_attn [kR * 2048];

// ---------------- tf32 helpers ----------------
__device__ __forceinline__ uint32_t f2tf(float f) {
    uint32_t r; asm("cvt.rna.tf32.f32 %0, %1;" : "=r"(r) : "f"(f)); return r;
}
__device__ __forceinline__ void fsplit(float f, uint32_t& hi, uint32_t& lo) {
    hi = f2tf(f);
    lo = f2tf(f - __uint_as_float(hi));
}
__device__ __forceinline__ void mma8(float& c0, float& c1, float& c2, float& c3,
                                     uint32_t a0, uint32_t a1, uint32_t a2, uint32_t a3,
                                     uint32_t b0, uint32_t b1) {
    asm volatile("mma.sync.aligned.m16n8k8.row.col.f32.tf32.tf32.f32 "
                 "{%0,%1,%2,%3},{%4,%5,%6,%7},{%8,%9},{%0,%1,%2,%3};"
                 : "+f"(c0), "+f"(c1), "+f"(c2), "+f"(c3)
                 : "r"(a0), "r"(a1), "r"(a2), "r"(a3), "r"(b0), "r"(b1));
}

// ================= GEMM: C[M,N] = A[M,K] @ B[K,N] + bias, tf32x3 =================
// 64x128 block tile, BK=32, 8 warps (2x4 of 32x32 warp tiles), 256 threads.
// M % 64 == 0, K % 32 == 0 at all call sites. N guarded.
constexpr int ASTR = 36;    // A smem stride (m-major rows of 32 k + pad)
constexpr int BSTR = 136;   // B smem stride (k rows of 128 n + pad)
constexpr int kGemmSmem = (64 * ASTR * 2 + 32 * BSTR * 2) * 4;  // 53248 bytes

__global__ __launch_bounds__(256, 2) void gemm_tf32x3_kernel(
    int M, int N, int K,
    const float* __restrict__ A, const float* __restrict__ B,
    const float* __restrict__ bias, float* __restrict__ C)
{
    extern __shared__ uint32_t smbuf[];
    uint32_t* Ah = smbuf;
    uint32_t* Al = Ah + 64 * ASTR;
    uint32_t* Bh = Al + 64 * ASTR;
    uint32_t* Bl = Bh + 32 * BSTR;

    const int tid = threadIdx.x, w = tid >> 5, lane = tid & 31;
    const int gid = lane >> 2, tig = lane & 3;
    const int m0 = (w >> 2) * 32, n0 = (w & 3) * 32;
    const int bR = blockIdx.y, bC = blockIdx.x;

    float acc[2][4][4];
#pragma unroll
    for (int mt = 0; mt < 2; mt++)
#pragma unroll
        for (int nt = 0; nt < 4; nt++)
#pragma unroll
            for (int e = 0; e < 4; e++) acc[mt][nt][e] = 0.0f;

    for (int k0 = 0; k0 < K; k0 += 32) {
        __syncthreads();
        // ---- stage A (64 x 32), split hi/lo ----
        {
            int r = tid >> 3, kc = (tid & 7) * 4;
#pragma unroll
            for (int p = 0; p < 2; p++) {
                int rr = r + p * 32;
                float4 a = *(const float4*)(A + (size_t)(bR * 64 + rr) * K + k0 + kc);
                uint4 h, l;
                fsplit(a.x, h.x, l.x); fsplit(a.y, h.y, l.y);
                fsplit(a.z, h.z, l.z); fsplit(a.w, h.w, l.w);
                *(uint4*)(Ah + rr * ASTR + kc) = h;
                *(uint4*)(Al + rr * ASTR + kc) = l;
            }
        }
        // ---- stage B (32 x 128), split hi/lo ----
        {
            int r = tid >> 5, c = (tid & 31) * 4;
            int gc = bC * 128 + c;
#pragma unroll
            for (int p = 0; p < 4; p++) {
                int rr = r + p * 8;
                float4 b = make_float4(0.f, 0.f, 0.f, 0.f);
                const float* bp = B + (size_t)(k0 + rr) * N + gc;
                if (gc + 3 < N) {
                    b = *(const float4*)bp;
                } else {
                    if (gc + 0 < N) b.x = bp[0];
                    if (gc + 1 < N) b.y = bp[1];
                    if (gc + 2 < N) b.z = bp[2];
                }
                uint4 h, l;
                fsplit(b.x, h.x, l.x); fsplit(b.y, h.y, l.y);
                fsplit(b.z, h.z, l.z); fsplit(b.w, h.w, l.w);
                *(uint4*)(Bh + rr * BSTR + c) = h;
                *(uint4*)(Bl + rr * BSTR + c) = l;
            }
        }
        __syncthreads();

#pragma unroll
        for (int ks = 0; ks < 4; ks++) {
            uint32_t ah[2][4], al[2][4], bh[4][2], bl[4][2];
#pragma unroll
            for (int mt = 0; mt < 2; mt++) {
                int mb = m0 + mt * 16;
                int kcol = ks * 8 + tig;
                ah[mt][0] = Ah[(mb + gid) * ASTR + kcol];
                ah[mt][1] = Ah[(mb + gid + 8) * ASTR + kcol];
                ah[mt][2] = Ah[(mb + gid) * ASTR + kcol + 4];
                ah[mt][3] = Ah[(mb + gid + 8) * ASTR + kcol + 4];
                al[mt][0] = Al[(mb + gid) * ASTR + kcol];
                al[mt][1] = Al[(mb + gid + 8) * ASTR + kcol];
                al[mt][2] = Al[(mb + gid) * ASTR + kcol + 4];
                al[mt][3] = Al[(mb + gid + 8) * ASTR + kcol + 4];
            }
#pragma unroll
            for (int nt = 0; nt < 4; nt++) {
                int nb = n0 + nt * 8 + gid;
                bh[nt][0] = Bh[(ks * 8 + tig) * BSTR + nb];
                bh[nt][1] = Bh[(ks * 8 + tig + 4) * BSTR + nb];
                bl[nt][0] = Bl[(ks * 8 + tig) * BSTR + nb];
                bl[nt][1] = Bl[(ks * 8 + tig + 4) * BSTR + nb];
            }
#pragma unroll
            for (int mt = 0; mt < 2; mt++)
#pragma unroll
                for (int nt = 0; nt < 4; nt++) {
                    float* c = acc[mt][nt];
                    mma8(c[0], c[1], c[2], c[3], ah[mt][0], ah[mt][1], ah[mt][2], ah[mt][3], bh[nt][0], bh[nt][1]);
                    mma8(c[0], c[1], c[2], c[3], ah[mt][0], ah[mt][1], ah[mt][2], ah[mt][3], bl[nt][0], bl[nt][1]);
                    mma8(c[0], c[1], c[2], c[3], al[mt][0], al[mt][1], al[mt][2], al[mt][3], bh[nt][0], bh[nt][1]);
                }
        }
    }

#pragma unroll
    for (int mt = 0; mt < 2; mt++)
#pragma unroll
        for (int nt = 0; nt < 4; nt++) {
            int row = bR * 64 + m0 + mt * 16 + gid;
            int col = bC * 128 + n0 + nt * 8 + tig * 2;
            if (col < N) {
                float b0 = bias[col], b1 = bias[col + 1];
                float2 v0 = make_float2(acc[mt][nt][0] + b0, acc[mt][nt][1] + b1);
                float2 v1 = make_float2(acc[mt][nt][2] + b0, acc[mt][nt][3] + b1);
                *(float2*)(C + (size_t)row * N + col) = v0;
                *(float2*)(C + (size_t)(row + 8) * N + col) = v1;
            }
        }
}

// ---------------- RMSNorm in place, width 128 ----------------
__global__ void rmsnorm_inplace_kernel(float* __restrict__ x, const float* __restrict__ w)
{
    const int row = blockIdx.x;
    const int tid = threadIdx.x;
    float v = x[(size_t)row * 128 + tid];
    float ss = v * v;
#pragma unroll
    for (int o = 16; o > 0; o >>= 1) ss += __shfl_xor_sync(0xffffffffu, ss, o);
    __shared__ float red[4];
    if ((tid & 31) == 0) red[tid >> 5] = ss;
    __syncthreads();
    float sum = red[0] + red[1] + red[2] + red[3];
    float inv = rsqrtf(sum * (1.0f / 128.0f) + kEps);
    x[(size_t)row * 128 + tid] = w[tid] * v * inv;
}

// ---------------- RoPE on q (in place) ----------------
__global__ void rope_q_kernel(float* __restrict__ q, const int* __restrict__ pos_ids)
{
    const int row = blockIdx.x;
    const int tid = threadIdx.x;  // 128 = 8 heads * 16 pairs
    const int h = tid >> 4, i = tid & 15;
    float pos = (float)pos_ids[row];
    float inv = expf(-((float)(2 * i) / 32.0f) * kLogTheta);
    float sv, cv;
    sincosf(pos * inv, &sv, &cv);
    float* base = q + (size_t)row * 1024 + 768 + h * 32;
    float xe = base[2 * i], xo = base[2 * i + 1];
    base[2 * i]     = xe * cv - xo * sv;
    base[2 * i + 1] = xe * sv + xo * cv;
}

// --------- ckv post: rmsnorm + k-rope ---------
__global__ void ckv_post_kernel(const float* __restrict__ ckv, const float* __restrict__ w,
                                const int* __restrict__ pos_ids,
                                float* __restrict__ ckvn, float* __restrict__ krope)
{
    const int row = blockIdx.x;
    const int tid = threadIdx.x;
    float v = ckv[(size_t)row * 192 + tid];
    float ss = v * v;
#pragma unroll
    for (int o = 16; o > 0; o >>= 1) ss += __shfl_xor_sync(0xffffffffu, ss, o);
    __shared__ float red[4];
    if ((tid & 31) == 0) red[tid >> 5] = ss;
    __syncthreads();
    float sum = red[0] + red[1] + red[2] + red[3];
    float inv = rsqrtf(sum * (1.0f / 128.0f) + kEps);
    ckvn[(size_t)row * 128 + tid] = w[tid] * v * inv;

    if (tid < 32) {
        const int i = tid;
        float pos = (float)pos_ids[row];
        float invf = expf(-((float)(2 * i) / 64.0f) * kLogTheta);
        float sv, cv;
        sincosf(pos * invf, &sv, &cv);
        const float* rb = ckv + (size_t)row * 192 + 128;
        float xe = rb[2 * i], xo = rb[2 * i + 1];
        krope[(size_t)row * 64 + 2 * i]     = xe * cv - xo * sv;
        krope[(size_t)row * 64 + 2 * i + 1] = xe * sv + xo * cv;
    }
}

// ================= tensor-core flash attention (tf32) =================
// Grid: (64, 8, 2): x = qtile*2 + vhalf. 4 warps; warp w owns query rows w*16..+15.
// Q frags live in registers for the whole block. K/V staged tf32 in smem.
constexpr int KLDs = 132;   // Ks stride
constexpr int VLDs = 136;   // Vs stride
constexpr int PLDs = 36;    // Ps stride (per warp)

__device__ __forceinline__ float qval(const float* __restrict__ q, size_t grow, int h, int d) {
    return (d < 96) ? q[grow * 1024 + h * 96 + d]
                    : q[grow * 1024 + 768 + h * 32 + (d - 96)];
}

__global__ __launch_bounds__(128, 2) void attn_tc_kernel(
    const float* __restrict__ q, const float* __restrict__ kvu,
    const float* __restrict__ krope, float* __restrict__ out)
{
    __shared__ uint32_t Ks[32 * KLDs];
    __shared__ uint32_t Vs[32 * VLDs];
    __shared__ uint32_t Ps[4 * 16 * PLDs];

    const int qt = blockIdx.x >> 1, vh = blockIdx.x & 1;
    const int h = blockIdx.y, b = blockIdx.z;
    const int tid = threadIdx.x, w = tid >> 5, lane = tid & 31;
    const int gid = lane >> 2, tig = lane & 3;
    const size_t rowbase = (size_t)b * kS;
    const int q0 = qt * 64, m0 = w * 16;

    // ---- preload Q fragments (tf32) into registers ----
    uint32_t qf[16][4];
    {
        size_t r0 = rowbase + q0 + m0 + gid;
#pragma unroll
        for (int ks = 0; ks < 16; ks++) {
            int d0 = ks * 8 + tig;
            qf[ks][0] = f2tf(qval(q, r0,     h, d0));
            qf[ks][1] = f2tf(qval(q, r0 + 8, h, d0));
            qf[ks][2] = f2tf(qval(q, r0,     h, d0 + 4));
            qf[ks][3] = f2tf(qval(q, r0 + 8, h, d0 + 4));
        }
    }

    float oacc[16][4];
#pragma unroll
    for (int nt = 0; nt < 16; nt++)
#pragma unroll
        for (int e = 0; e < 4; e++) oacc[nt][e] = 0.0f;
    float mrow0 = -INFINITY, mrow1 = -INFINITY, lrow0 = 0.0f, lrow1 = 0.0f;

    for (int kt = 0; kt < kS / 32; kt++) {
        __syncthreads();
        // ---- stage K (32x128) and V half (32x128), tf32 ----
        {
            int r = tid >> 5, c4 = (tid & 31) * 4;
#pragma unroll
            for (int p = 0; p < 8; p++) {
                int j = r + p * 4;
                size_t grow = rowbase + kt * 32 + j;
                float4 kv = (c4 < 64)
                    ? *(const float4*)(kvu + grow * 2560 + h * 64 + c4)
                    : *(const float4*)(krope + grow * 64 + (c4 - 64));
                uint4 kk;
                kk.x = f2tf(kv.x); kk.y = f2tf(kv.y); kk.z = f2tf(kv.z); kk.w = f2tf(kv.w);
                *(uint4*)(Ks + j * KLDs + c4) = kk;
                float4 vv = *(const float4*)(kvu + grow * 2560 + 512 + h * 256 + vh * 128 + c4);
                uint4 vt;
                vt.x = f2tf(vv.x); vt.y = f2tf(vv.y); vt.z = f2tf(vv.z); vt.w = f2tf(vv.w);
                *(uint4*)(Vs + j * VLDs + c4) = vt;
            }
        }
        __syncthreads();

        // ---- S = Q @ K^T ----
        float sacc[4][4];
#pragma unroll
        for (int nt = 0; nt < 4; nt++)
#pragma unroll
            for (int e = 0; e < 4; e++) sacc[nt][e] = 0.0f;
#pragma unroll
        for (int ks = 0; ks < 16; ks++) {
#pragma unroll
            for (int nt = 0; nt < 4; nt++) {
                uint32_t b0 = Ks[(nt * 8 + gid) * KLDs + ks * 8 + tig];
                uint32_t b1 = Ks[(nt * 8 + gid) * KLDs + ks * 8 + tig + 4];
                mma8(sacc[nt][0], sacc[nt][1], sacc[nt][2], sacc[nt][3],
                     qf[ks][0], qf[ks][1], qf[ks][2], qf[ks][3], b0, b1);
            }
        }

        // ---- online softmax ----
        float mx0 = -INFINITY, mx1 = -INFINITY;
#pragma unroll
        for (int nt = 0; nt < 4; nt++) {
            sacc[nt][0] *= kScale; sacc[nt][1] *= kScale;
            sacc[nt][2] *= kScale; sacc[nt][3] *= kScale;
            mx0 = fmaxf(mx0, fmaxf(sacc[nt][0], sacc[nt][1]));
            mx1 = fmaxf(mx1, fmaxf(sacc[nt][2], sacc[nt][3]));
        }
        mx0 = fmaxf(mx0, __shfl_xor_sync(0xffffffffu, mx0, 1));
        mx0 = fmaxf(mx0, __shfl_xor_sync(0xffffffffu, mx0, 2));
        mx1 = fmaxf(mx1, __shfl_xor_sync(0xffffffffu, mx1, 1));
        mx1 = fmaxf(mx1, __shfl_xor_sync(0xffffffffu, mx1, 2));
        float mn0 = fmaxf(mrow0, mx0), mn1 = fmaxf(mrow1, mx1);
        float cor0 = __expf(mrow0 - mn0), cor1 = __expf(mrow1 - mn1);
        float ps0 = 0.0f, ps1 = 0.0f;
#pragma unroll
        for (int nt = 0; nt < 4; nt++) {
            sacc[nt][0] = __expf(sacc[nt][0] - mn0);
            sacc[nt][1] = __expf(sacc[nt][1] - mn0);
            sacc[nt][2] = __expf(sacc[nt][2] - mn1);
            sacc[nt][3] = __expf(sacc[nt][3] - mn1);
            ps0 += sacc[nt][0] + sacc[nt][1];
            ps1 += sacc[nt][2] + sacc[nt][3];
        }
        ps0 += __shfl_xor_sync(0xffffffffu, ps0, 1);
        ps0 += __shfl_xor_sync(0xffffffffu, ps0, 2);
        ps1 += __shfl_xor_sync(0xffffffffu, ps1, 1);
        ps1 += __shfl_xor_sync(0xffffffffu, ps1, 2);
        lrow0 = lrow0 * cor0 + ps0;
        lrow1 = lrow1 * cor1 + ps1;
        mrow0 = mn0; mrow1 = mn1;
#pragma unroll
        for (int nt = 0; nt < 16; nt++) {
            oacc[nt][0] *= cor0; oacc[nt][1] *= cor0;
            oacc[nt][2] *= cor1; oacc[nt][3] *= cor1;
        }

        // ---- P -> smem (tf32, A-frag layout) ----
        uint32_t* pw = Ps + w * 16 * PLDs;
#pragma unroll
        for (int nt = 0; nt < 4; nt++) {
            int c = nt * 8 + tig * 2;
            pw[gid * PLDs + c]           = f2tf(sacc[nt][0]);
            pw[gid * PLDs + c + 1]       = f2tf(sacc[nt][1]);
            pw[(gid + 8) * PLDs + c]     = f2tf(sacc[nt][2]);
            pw[(gid + 8) * PLDs + c + 1] = f2tf(sacc[nt][3]);
        }
        __syncwarp();

        // ---- O += P @ V ----
#pragma unroll
        for (int ks = 0; ks < 4; ks++) {
            uint32_t a0 = pw[gid * PLDs + ks * 8 + tig];
            uint32_t a1 = pw[(gid + 8) * PLDs + ks * 8 + tig];
            uint32_t a2 = pw[gid * PLDs + ks * 8 + tig + 4];
            uint32_t a3 = pw[(gid + 8) * PLDs + ks * 8 + tig + 4];
#pragma unroll
            for (int nt = 0; nt < 16; nt++) {
                uint32_t b0 = Vs[(ks * 8 + tig) * VLDs + nt * 8 + gid];
                uint32_t b1 = Vs[(ks * 8 + tig + 4) * VLDs + nt * 8 + gid];
                mma8(oacc[nt][0], oacc[nt][1], oacc[nt][2], oacc[nt][3],
                     a0, a1, a2, a3, b0, b1);
            }
        }
    }

    // ---- epilogue ----
    const float il0 = 1.0f / lrow0, il1 = 1.0f / lrow1;
    size_t row0 = rowbase + q0 + m0 + gid;
#pragma unroll
    for (int nt = 0; nt < 16; nt++) {
        int col = h * 256 + vh * 128 + nt * 8 + tig * 2;
        float2 v0 = make_float2(oacc[nt][0] * il0, oacc[nt][1] * il0);
        float2 v1 = make_float2(oacc[nt][2] * il1, oacc[nt][3] * il1);
        *(float2*)(out + row0 * 2048 + col) = v0;
        *(float2*)(out + (row0 + 8) * 2048 + col) = v1;
    }
}

// ---------------- launch ----------------
extern "C" void kernel_launch(void* const* d_in, const int* in_sizes, int n_in,
                              void* d_out, int out_size)
{
    const float* x         = (const float*)d_in[0];
    const int*   pos       = (const int*)  d_in[1];
    const float* w_dq_w    = (const float*)d_in[2];
    const float* w_dq_b    = (const float*)d_in[3];
    const float* q_norm_w  = (const float*)d_in[4];
    const float* w_uq_w    = (const float*)d_in[5];
    const float* w_uq_b    = (const float*)d_in[6];
    const float* w_dkv_w   = (const float*)d_in[7];
    const float* w_dkv_b   = (const float*)d_in[8];
    const float* kv_norm_w = (const float*)d_in[9];
    const float* w_ukuv_w  = (const float*)d_in[10];
    const float* w_ukuv_b  = (const float*)d_in[11];
    const float* w_o_w     = (const float*)d_in[12];
    const float* w_o_b     = (const float*)d_in[13];
    float* out = (float*)d_out;

    float *cq, *qb, *ckv, *ckvn, *krope, *kvu, *attn;
    cudaGetSymbolAddress((void**)&cq,    g_cq);
    cudaGetSymbolAddress((void**)&qb,    g_q);
    cudaGetSymbolAddress((void**)&ckv,   g_ckv);
    cudaGetSymbolAddress((void**)&ckvn,  g_ckvn);
    cudaGetSymbolAddress((void**)&krope, g_krope);
    cudaGetSymbolAddress((void**)&kvu,   g_kvu);
    cudaGetSymbolAddress((void**)&attn,  g_attn);

    cudaFuncSetAttribute(gemm_tf32x3_kernel,
                         cudaFuncAttributeMaxDynamicSharedMemorySize, kGemmSmem);

    // Q path
    gemm_tf32x3_kernel<<<dim3(1, kR / 64), 256, kGemmSmem>>>(kR, 128, 1024, x, w_dq_w, w_dq_b, cq);
    rmsnorm_inplace_kernel<<<kR, 128>>>(cq, q_norm_w);
    gemm_tf32x3_kernel<<<dim3(8, kR / 64), 256, kGemmSmem>>>(kR, 1024, 128, cq, w_uq_w, w_uq_b, qb);
    rope_q_kernel<<<kR, 128>>>(qb, pos);

    // KV path
    gemm_tf32x3_kernel<<<dim3(2, kR / 64), 256, kGemmSmem>>>(kR, 192, 1024, x, w_dkv_w, w_dkv_b, ckv);
    ckv_post_kernel<<<kR, 128>>>(ckv, kv_norm_w, pos, ckvn, krope);
    gemm_tf32x3_kernel<<<dim3(20, kR / 64), 256, kGemmSmem>>>(kR, 2560, 128, ckvn, w_ukuv_w, w_ukuv_b, kvu);

    // Attention (tensor core, V-dim split in 2)
    attn_tc_kernel<<<dim3(64, 8, 2), 128>>>(qb, kvu, krope, attn);

    // Output projection
    gemm_tf32x3_kernel<<<dim3(8, kR / 64), 256, kGemmSmem>>>(kR, 1024, 2048, attn, w_o_w, w_o_b, out);
}